// round 8
// baseline (speedup 1.0000x reference)
#include <cuda_runtime.h>
#include <cstdint>

// Problem constants
#define B 8
#define N 4096
#define C 1024
#define H 16
#define D 64
#define SCALE 0.125f

typedef unsigned long long ull;

// Scratch (no cudaMalloc allowed)
__device__ float g_k[B * C];        // [b][h*D+d]
__device__ float g_v[B * C];
__device__ float g_u[B * H * C];    // [b][h][c]  folded Wq*k
__device__ float g_M[B * H * C];    // [b][h][c]  folded Wp*v
__device__ ull g_attnd[B * N * H];  // duplicated f32x2 sigmoid gates, 4MB

// Packed fp32x2 helpers (sm_103a)
#define FMA2(acc, a, bb) asm("fma.rn.f32x2 %0, %1, %2, %0;" : "+l"(acc) : "l"(a), "l"(bb))
#define ADD2(d, a, bb)   asm("add.rn.f32x2 %0, %1, %2;"     : "=l"(d)   : "l"(a), "l"(bb))

// Volatile loads: ptxas cannot sink these -> guaranteed front-batched MLP.
#define LDGV4(dst, ptr)                                                     \
  asm volatile("ld.global.nc.v4.f32 {%0,%1,%2,%3}, [%4];"                   \
               : "=f"(dst.x), "=f"(dst.y), "=f"(dst.z), "=f"(dst.w)         \
               : "l"(ptr))
#define LDGF(dst, ptr) \
  asm volatile("ld.global.nc.f32 %0, [%1];" : "=f"(dst) : "l"(ptr))

#define CPASYNC16(smem_u32, gptr)                                           \
  asm volatile("cp.async.cg.shared.global [%0], [%1], 16;" ::"r"(smem_u32), \
               "l"(gptr))
#define COMMIT() asm volatile("cp.async.commit_group;" ::: "memory")
#define WAITG(n) asm volatile("cp.async.wait_group %0;" ::"n"(n) : "memory")

// ---------------------------------------------------------------------------
// P1: k = emb @ Wk.T, v = emb @ Wv.T.   (unchanged — protected win)
// ---------------------------------------------------------------------------
__global__ void __launch_bounds__(128) precompute_kv(
    const float* __restrict__ emb, const float* __restrict__ Wk,
    const float* __restrict__ Wv) {
  int gw = (blockIdx.x * 128 + threadIdx.x) >> 5;  // 0..4095
  int lane = threadIdx.x & 31;
  int sel = gw >> 11;
  int rem = gw & 2047;
  int j = rem >> 1;
  int bh = (rem & 1) * 4;
  const float* W = sel ? Wv : Wk;
  float* dst = sel ? g_v : g_k;
  const float4* w4 = reinterpret_cast<const float4*>(W + j * C);
  const float4* e4 = reinterpret_cast<const float4*>(emb);

  float4 wv[8];
#pragma unroll
  for (int i = 0; i < 8; i++) LDGV4(wv[i], w4 + lane + 32 * i);

  float acc[4];
#pragma unroll
  for (int b = 0; b < 4; b++) acc[b] = 0.f;
#pragma unroll
  for (int b = 0; b < 4; b++) {
    float4 e[8];
#pragma unroll
    for (int i = 0; i < 8; i++) e[i] = e4[(bh + b) * 256 + lane + 32 * i];
#pragma unroll
    for (int i = 0; i < 8; i++)
      acc[b] += wv[i].x * e[i].x + wv[i].y * e[i].y + wv[i].z * e[i].z +
                wv[i].w * e[i].w;
  }
#pragma unroll
  for (int b = 0; b < 4; b++)
    for (int s = 16; s; s >>= 1) acc[b] += __shfl_xor_sync(0xffffffffu, acc[b], s);
  if (lane == 0) {
#pragma unroll
    for (int b = 0; b < 4; b++) dst[(bh + b) * C + j] = acc[b];
  }
}

// ---------------------------------------------------------------------------
// P2: u/M fold.  grid (4,16,2): batch-group of 4 -> Wq/Wp read only 2x.
// ---------------------------------------------------------------------------
__global__ void __launch_bounds__(256) precompute_uM(
    const float* __restrict__ Wq, const float* __restrict__ Wp) {
  __shared__ float kk[4][D];
  __shared__ float vv[4][D];
  int h = blockIdx.y;
  int bg = blockIdx.z * 4;
  int c = blockIdx.x * 256 + threadIdx.x;
  {
    int b = threadIdx.x >> 6, d = threadIdx.x & 63;
    kk[b][d] = g_k[(bg + b) * C + h * D + d];
    vv[b][d] = g_v[(bg + b) * C + h * D + d];
  }
  __syncthreads();

  float acc[4];
#pragma unroll
  for (int b = 0; b < 4; b++) acc[b] = 0.f;
#pragma unroll
  for (int d0 = 0; d0 < D; d0 += 16) {
    float wq[16];
#pragma unroll
    for (int jj = 0; jj < 16; jj++) LDGF(wq[jj], Wq + (h * D + d0 + jj) * C + c);
#pragma unroll
    for (int jj = 0; jj < 16; jj++)
#pragma unroll
      for (int b = 0; b < 4; b++) acc[b] += wq[jj] * kk[b][d0 + jj];
  }
#pragma unroll
  for (int b = 0; b < 4; b++) g_u[((bg + b) * H + h) * C + c] = acc[b];

  float acc2[4];
#pragma unroll
  for (int b = 0; b < 4; b++) acc2[b] = 0.f;
  const float4* wp4 = reinterpret_cast<const float4*>(Wp + c * C + h * D);
#pragma unroll
  for (int i0 = 0; i0 < 16; i0 += 8) {
    float4 wp[8];
#pragma unroll
    for (int i = 0; i < 8; i++) LDGV4(wp[i], wp4 + i0 + i);
#pragma unroll
    for (int i = 0; i < 8; i++) {
      int d = (i0 + i) * 4;
#pragma unroll
      for (int b = 0; b < 4; b++)
        acc2[b] += wp[i].x * vv[b][d] + wp[i].y * vv[b][d + 1] +
                   wp[i].z * vv[b][d + 2] + wp[i].w * vv[b][d + 3];
    }
  }
#pragma unroll
  for (int b = 0; b < 4; b++) g_M[((bg + b) * H + h) * C + c] = acc2[b];
}

// ---------------------------------------------------------------------------
// PASS A: attn[b,n,h] = sigmoid(SCALE * fea[b,n,:] . u[b,h,:]).
// 144 blocks (18/batch), 512 threads (16 warps = 4/SMSP for latency hiding).
// u[b] resident in smem; fea streamed through a 3-slot ring of 32rx256c
// chunks (ring slot = q%3, column chunk = q&3).  One barrier per chunk.
// ---------------------------------------------------------------------------
#define NBLK_A 144
#define BPB 18                 // blocks per batch
#define CHSTR 260              // floats per chunk row (256 + pad)
#define CHF (32 * CHSTR)       // 8320 floats per chunk slot
#define NSLOT 3
#define U_FLOATS (H * C)       // 16384
#define PART_FLOATS (16 * 32 * 17)  // 8704
#define SMEM_A ((U_FLOATS + NSLOT * CHF + PART_FLOATS) * 4)  // 200192 B

__global__ void __launch_bounds__(512, 1) attn_pass(
    const float* __restrict__ fea) {
  extern __shared__ __align__(16) float sm[];
  float* u_s = sm;                    // [h][c]
  float* ring = sm + U_FLOATS;        // 3 x CHF
  float* part = ring + NSLOT * CHF;   // [w16][r32][17]

  const int t = threadIdx.x;
  const int w = t >> 5;   // 0..15
  const int l = t & 31;   // row

  const int batch = blockIdx.x / BPB;
  const int bi = blockIdx.x % BPB;
  const int ts = batch * 128 + (bi * 128) / BPB;
  const int te = batch * 128 + ((bi + 1) * 128) / BPB;
  const int nQ = (te - ts) * 4;

  // chunk q: tile ts+q/4, cols (q&3)*256, ring slot q%3.
  // 2048 16B transfers / 512 threads = 4 each.
#define ISSUE_Q(q)                                                          \
  {                                                                         \
    const float* srcb =                                                     \
        fea + (size_t)(ts + (q) / 4) * 32768 + ((q) & 3) * 256;             \
    float* db = ring + ((q) % 3) * CHF;                                     \
    _Pragma("unroll") for (int i = 0; i < 4; i++) {                         \
      int idx = t + 512 * i;                                                \
      int r = idx >> 6;                                                     \
      int c4 = idx & 63;                                                    \
      unsigned ds =                                                         \
          (unsigned)__cvta_generic_to_shared(db + r * CHSTR + c4 * 4);      \
      CPASYNC16(ds, srcb + r * 1024 + c4 * 4);                              \
    }                                                                       \
  }

  // Prologue: group0 = (u + chunk0), group1 = chunk1.
  {
    const float4* gu4 = reinterpret_cast<const float4*>(g_u + batch * U_FLOATS);
#pragma unroll
    for (int i = 0; i < 8; i++) {
      int idx = t + 512 * i;
      unsigned ds = (unsigned)__cvta_generic_to_shared(u_s + idx * 4);
      CPASYNC16(ds, gu4 + idx);
    }
  }
  ISSUE_Q(0); COMMIT();
  ISSUE_Q(1); COMMIT();

  ull p2[H];

  for (int q = 0; q < nQ; ++q) {
    WAITG(1);         // chunk q (and for q==0, u) landed
    __syncthreads();  // all threads past chunk q-1 -> slot (q+2)%3 is free
    if (q + 2 < nQ) { ISSUE_Q(q + 2); }
    COMMIT();         // one commit per iteration (possibly empty)

    const int ck = q & 3;
    if (ck == 0) {
#pragma unroll
      for (int h = 0; h < H; h++) p2[h] = 0ull;
    }

    // warp w owns f4-cols [w*4, w*4+4) of this 256-col chunk; lane = row.
    const float* fp = ring + (q % 3) * CHF + l * CHSTR + w * 16;
    const float* up = u_s + ck * 256 + w * 16;
#pragma unroll
    for (int j = 0; j < 4; j++) {
      ulonglong2 f = *reinterpret_cast<const ulonglong2*>(fp + j * 4);
#pragma unroll
      for (int h = 0; h < H; h++) {
        ulonglong2 uu =
            *reinterpret_cast<const ulonglong2*>(up + h * C + j * 4);
        FMA2(p2[h], f.x, uu.x);
        FMA2(p2[h], f.y, uu.y);
      }
    }

    if (ck == 3) {  // tile finished: reduce + sigmoid + store
      const int tile = ts + (q >> 2);
#pragma unroll
      for (int h = 0; h < H; h++) {
        float lo, hi;
        asm("mov.b64 {%0,%1}, %2;" : "=f"(lo), "=f"(hi) : "l"(p2[h]));
        part[(w * 32 + l) * 17 + h] = lo + hi;
      }
      __syncthreads();
      {
        int r = t >> 4, h = t & 15;  // 512 threads = 32 rows x 16 heads
        float s = 0.f;
#pragma unroll
        for (int ww = 0; ww < 16; ww++) s += part[(ww * 32 + r) * 17 + h];
        float a = 1.f / (1.f + __expf(-s * SCALE));
        ull ad;
        asm("mov.b64 %0, {%1,%1};" : "=l"(ad) : "f"(a));
        g_attnd[(tile * 32 + r) * H + h] = ad;
      }
    }
  }
}

// ---------------------------------------------------------------------------
// PASS B: out = fea + bp + attn @ M.  512 blocks x 512 thr, 2 cols/thread
// (M slice = 16 ull = 32 regs -> 2 blocks/SM, 32 warps).  4-row prefetch.
// ---------------------------------------------------------------------------
__global__ void __launch_bounds__(512, 2) out_pass(
    const float* __restrict__ fea, const float* __restrict__ bp,
    float* __restrict__ out) {
  __shared__ __align__(16) ull attn_s[64 * H];  // 8KB

  const int t = threadIdx.x;
  const size_t row0 = (size_t)blockIdx.x * 64;
  const int b = (int)(row0 >> 12);
  const int c0 = t * 2;

  // stage attn for 64 rows: 512 ulonglong2 / 512 threads = 1 each
  {
    const ulonglong2* src =
        reinterpret_cast<const ulonglong2*>(g_attnd + row0 * H);
    reinterpret_cast<ulonglong2*>(attn_s)[t] = src[t];
  }

  ull bpv = *reinterpret_cast<const ull*>(bp + c0);
  ull M2[H];
#pragma unroll
  for (int h = 0; h < H; h++)
    M2[h] = *reinterpret_cast<const ull*>(g_M + (b * H + h) * C + c0);
  __syncthreads();

  const float* fb = fea + row0 * C + c0;
  float* ob = out + row0 * C + c0;

  // 4-deep row prefetch ring
  ull pf[4];
#pragma unroll
  for (int i = 0; i < 4; i++)
    pf[i] = *reinterpret_cast<const ull*>(fb + i * C);

#pragma unroll 4
  for (int r = 0; r < 64; r++) {
    ull f = pf[r & 3];
    if (r + 4 < 64) pf[r & 3] = *reinterpret_cast<const ull*>(fb + (r + 4) * C);
    ull o;
    ADD2(o, f, bpv);
    const ull* ar = attn_s + r * H;
#pragma unroll
    for (int hg = 0; hg < 8; hg++) {
      ulonglong2 a2 = *reinterpret_cast<const ulonglong2*>(ar + hg * 2);
      FMA2(o, a2.x, M2[hg * 2]);
      FMA2(o, a2.y, M2[hg * 2 + 1]);
    }
    *reinterpret_cast<ull*>(ob + r * C) = o;
  }
}

// ---------------------------------------------------------------------------
extern "C" void kernel_launch(void* const* d_in, const int* in_sizes, int n_in,
                              void* d_out, int out_size) {
  const float* fea = (const float*)d_in[0];
  const float* emb = (const float*)d_in[1];
  const float* Wq  = (const float*)d_in[2];
  const float* Wk  = (const float*)d_in[3];
  const float* Wv  = (const float*)d_in[4];
  const float* Wp  = (const float*)d_in[5];
  const float* bp  = (const float*)d_in[6];
  float* out = (float*)d_out;

  cudaFuncSetAttribute(attn_pass, cudaFuncAttributeMaxDynamicSharedMemorySize,
                       SMEM_A);

  precompute_kv<<<1024, 128>>>(emb, Wk, Wv);
  precompute_uM<<<dim3(4, H, 2), 256>>>(Wq, Wp);
  attn_pass<<<NBLK_A, 512, SMEM_A>>>(fea);
  out_pass<<<512, 512>>>(fea, bp, out);
}

// round 11
// speedup vs baseline: 1.7396x; 1.7396x over previous
#include <cuda_runtime.h>
#include <cstdint>

// Problem constants
#define B 8
#define N 4096
#define C 1024
#define H 16
#define D 64
#define SCALE 0.125f

typedef unsigned long long ull;

// Scratch (no cudaMalloc allowed)
__device__ float g_k[B * C];      // [b][h*D+d]
__device__ float g_v[B * C];
__device__ float g_u[B * H * C];  // [b][h][c]  folded Wq*k
__device__ float g_M[B * H * C];  // [b][h][c]  folded Wp*v

// Packed fp32x2 helpers (sm_103a)
#define FMA2(acc, a, bb) asm("fma.rn.f32x2 %0, %1, %2, %0;" : "+l"(acc) : "l"(a), "l"(bb))
#define ADD2(d, a, bb)   asm("add.rn.f32x2 %0, %1, %2;"     : "=l"(d)   : "l"(a), "l"(bb))

// Volatile loads: ptxas cannot sink these -> guaranteed front-batched MLP.
#define LDGV4(dst, ptr)                                                     \
  asm volatile("ld.global.nc.v4.f32 {%0,%1,%2,%3}, [%4];"                   \
               : "=f"(dst.x), "=f"(dst.y), "=f"(dst.z), "=f"(dst.w)         \
               : "l"(ptr))
#define LDGF(dst, ptr) \
  asm volatile("ld.global.nc.f32 %0, [%1];" : "=f"(dst) : "l"(ptr))

#define CPASYNC16(smem_u32, gptr)                                           \
  asm volatile("cp.async.cg.shared.global [%0], [%1], 16;" ::"r"(smem_u32), \
               "l"(gptr))
#define COMMIT() asm volatile("cp.async.commit_group;" ::: "memory")
#define WAITG(n) asm volatile("cp.async.wait_group %0;" ::"n"(n) : "memory")

// ---------------------------------------------------------------------------
// P1: k = emb @ Wk.T, v = emb @ Wv.T.   (protected win)
// ---------------------------------------------------------------------------
__global__ void __launch_bounds__(128) precompute_kv(
    const float* __restrict__ emb, const float* __restrict__ Wk,
    const float* __restrict__ Wv) {
  int gw = (blockIdx.x * 128 + threadIdx.x) >> 5;  // 0..4095
  int lane = threadIdx.x & 31;
  int sel = gw >> 11;
  int rem = gw & 2047;
  int j = rem >> 1;
  int bh = (rem & 1) * 4;
  const float* W = sel ? Wv : Wk;
  float* dst = sel ? g_v : g_k;
  const float4* w4 = reinterpret_cast<const float4*>(W + j * C);
  const float4* e4 = reinterpret_cast<const float4*>(emb);

  float4 wv[8];
#pragma unroll
  for (int i = 0; i < 8; i++) LDGV4(wv[i], w4 + lane + 32 * i);

  float acc[4];
#pragma unroll
  for (int b = 0; b < 4; b++) acc[b] = 0.f;
#pragma unroll
  for (int b = 0; b < 4; b++) {
    float4 e[8];
#pragma unroll
    for (int i = 0; i < 8; i++) e[i] = e4[(bh + b) * 256 + lane + 32 * i];
#pragma unroll
    for (int i = 0; i < 8; i++)
      acc[b] += wv[i].x * e[i].x + wv[i].y * e[i].y + wv[i].z * e[i].z +
                wv[i].w * e[i].w;
  }
#pragma unroll
  for (int b = 0; b < 4; b++)
    for (int s = 16; s; s >>= 1) acc[b] += __shfl_xor_sync(0xffffffffu, acc[b], s);
  if (lane == 0) {
#pragma unroll
    for (int b = 0; b < 4; b++) dst[(bh + b) * C + j] = acc[b];
  }
}

// ---------------------------------------------------------------------------
// P2: u/M fold.  grid (4,16,2).   (protected)
// ---------------------------------------------------------------------------
__global__ void __launch_bounds__(256) precompute_uM(
    const float* __restrict__ Wq, const float* __restrict__ Wp) {
  __shared__ float kk[4][D];
  __shared__ float vv[4][D];
  int h = blockIdx.y;
  int bg = blockIdx.z * 4;
  int c = blockIdx.x * 256 + threadIdx.x;
  {
    int b = threadIdx.x >> 6, d = threadIdx.x & 63;
    kk[b][d] = g_k[(bg + b) * C + h * D + d];
    vv[b][d] = g_v[(bg + b) * C + h * D + d];
  }
  __syncthreads();

  float acc[4];
#pragma unroll
  for (int b = 0; b < 4; b++) acc[b] = 0.f;
#pragma unroll
  for (int d0 = 0; d0 < D; d0 += 16) {
    float wq[16];
#pragma unroll
    for (int jj = 0; jj < 16; jj++) LDGF(wq[jj], Wq + (h * D + d0 + jj) * C + c);
#pragma unroll
    for (int jj = 0; jj < 16; jj++)
#pragma unroll
      for (int b = 0; b < 4; b++) acc[b] += wq[jj] * kk[b][d0 + jj];
  }
#pragma unroll
  for (int b = 0; b < 4; b++) g_u[((bg + b) * H + h) * C + c] = acc[b];

  float acc2[4];
#pragma unroll
  for (int b = 0; b < 4; b++) acc2[b] = 0.f;
  const float4* wp4 = reinterpret_cast<const float4*>(Wp + c * C + h * D);
#pragma unroll
  for (int i0 = 0; i0 < 16; i0 += 8) {
    float4 wp[8];
#pragma unroll
    for (int i = 0; i < 8; i++) LDGV4(wp[i], wp4 + i0 + i);
#pragma unroll
    for (int i = 0; i < 8; i++) {
      int d = (i0 + i) * 4;
#pragma unroll
      for (int b = 0; b < 4; b++)
        acc2[b] += wp[i].x * vv[b][d] + wp[i].y * vv[b][d + 1] +
                   wp[i].z * vv[b][d + 2] + wp[i].w * vv[b][d + 3];
    }
  }
#pragma unroll
  for (int b = 0; b < 4; b++) g_M[((bg + b) * H + h) * C + c] = acc2[b];
}

// ---------------------------------------------------------------------------
// FUSED main: per 16-row tile: phase1 scores -> sigmoid -> phase2 output.
// 144 batch-aligned blocks x 256 threads.  Double-buffered tiles: tile t+1
// streams while tile t computes; tile t+2 issued right after phase2(t).
// u[b] resident in smem (loaded once per block), M[b] slice in registers.
// PART stride = 20 floats (80B, float4-aligned — the R9 crash was float4
// stores at stride 17 = 68B).
// ---------------------------------------------------------------------------
#define NBLK 144
#define BPB 18                   // blocks per batch
#define TPB 256                  // 16-row tiles per batch
#define TSTR 1028                // floats per buffered row
#define BUFF (16 * TSTR)         // 16448 floats per tile buffer
#define U_FLOATS (H * C)         // 16384
#define PSTR 20
#define PART_FLOATS (8 * 16 * PSTR)  // 2560
// smem: u + 2 buffers + part + attn  = 209408 B
#define SMEM_MAIN ((U_FLOATS + 2 * BUFF + PART_FLOATS) * 4 + 16 * H * 8)

__global__ void __launch_bounds__(256, 1) gate_fused(
    const float* __restrict__ fea, const float* __restrict__ bp,
    float* __restrict__ out) {
  extern __shared__ __align__(16) float sm[];
  float* u_s = sm;                                     // [h][1024]
  float* bufs = sm + U_FLOATS;                         // 2 x BUFF
  float* part = bufs + 2 * BUFF;                       // [w8][r16][PSTR]
  ull* attn_d = reinterpret_cast<ull*>(part + PART_FLOATS);  // [r16][h16]

  const int t = threadIdx.x;
  const int w = t >> 5;
  const int l = t & 31;
  const int row = l & 15;   // phase-1 row
  const int jh = l >> 4;    // phase-1 column half
  const int c0 = t * 4;     // phase-2 columns

  const int batch = blockIdx.x / BPB;
  const int bi = blockIdx.x % BPB;
  const int ts = batch * TPB + (bi * TPB) / BPB;
  const int te = batch * TPB + ((bi + 1) * TPB) / BPB;

  // issue one 16x1024 tile (4096 x 16B / 256 thr = 16 each) into buf (T&1)
#define ISSUE_T(T)                                                          \
  {                                                                         \
    const float* srcb = fea + (size_t)(T) * 16384;                          \
    float* db = bufs + ((T) & 1) * BUFF;                                    \
    _Pragma("unroll") for (int i = 0; i < 16; i++) {                        \
      int idx = t + 256 * i;                                                \
      int r = idx >> 8;                                                     \
      int c4 = idx & 255;                                                   \
      unsigned ds =                                                         \
          (unsigned)__cvta_generic_to_shared(db + r * TSTR + c4 * 4);       \
      CPASYNC16(ds, srcb + r * 1024 + c4 * 4);                              \
    }                                                                       \
  }

  // Prologue: group0 = u[b], group1 = tile ts, group2 = tile ts+1.
  {
    const float4* gu4 = reinterpret_cast<const float4*>(g_u + batch * U_FLOATS);
#pragma unroll
    for (int i = 0; i < 16; i++) {
      int idx = t + 256 * i;
      unsigned ds = (unsigned)__cvta_generic_to_shared(u_s + idx * 4);
      CPASYNC16(ds, gu4 + idx);
    }
  }
  COMMIT();
  ISSUE_T(ts); COMMIT();
  ISSUE_T(ts + 1); COMMIT();

  // constants for phase 2
  ulonglong2 bpv = *reinterpret_cast<const ulonglong2*>(bp + c0);
  ulonglong2 M2[H];
#pragma unroll
  for (int h = 0; h < H; h++)
    M2[h] =
        *reinterpret_cast<const ulonglong2*>(g_M + (batch * H + h) * C + c0);

  for (int tile = ts; tile < te; ++tile) {
    WAITG(1);         // tile's buffer (and u on iter 0) landed
    __syncthreads();  // data visible to all; prior phase2 fully done

    const float* fb = bufs + (tile & 1) * BUFF;

    // ---- Phase 1: scores.  thread = (row, jh); warp covers f4-cols
    //      [w*32, w*32+32); per-thread f4 set: w*32 + cl*8 + jh*4 + jj.
    //      Warp's two u addresses per load differ by 64B -> 1 LDS wavefront.
    ull p2[H];
#pragma unroll
    for (int h = 0; h < H; h++) p2[h] = 0ull;

    const float* frow = fb + row * TSTR;
#pragma unroll
    for (int cl = 0; cl < 4; cl++) {
#pragma unroll
      for (int jj = 0; jj < 4; jj++) {
        const int c4 = w * 32 + cl * 8 + jh * 4 + jj;
        ulonglong2 f = *reinterpret_cast<const ulonglong2*>(frow + c4 * 4);
#pragma unroll
        for (int h = 0; h < H; h++) {
          ulonglong2 uu =
              *reinterpret_cast<const ulonglong2*>(u_s + h * C + c4 * 4);
          FMA2(p2[h], f.x, uu.x);
          FMA2(p2[h], f.y, uu.y);
        }
      }
    }
    // fold packed halves; combine the two jh halves via shuffle
    float s[H];
#pragma unroll
    for (int h = 0; h < H; h++) {
      float lo, hi;
      asm("mov.b64 {%0,%1}, %2;" : "=f"(lo), "=f"(hi) : "l"(p2[h]));
      s[h] = lo + hi;
      s[h] += __shfl_xor_sync(0xffffffffu, s[h], 16);
    }
    if (jh == 0) {
      float* pp = part + (w * 16 + row) * PSTR;
#pragma unroll
      for (int h4 = 0; h4 < 4; h4++)
        *reinterpret_cast<float4*>(pp + h4 * 4) = make_float4(
            s[h4 * 4], s[h4 * 4 + 1], s[h4 * 4 + 2], s[h4 * 4 + 3]);
    }
    __syncthreads();

    // reduce across 8 warps + sigmoid -> duplicated f32x2 attn (16r x 16h)
    {
      int r = t >> 4, h = t & 15;
      float sum = 0.f;
#pragma unroll
      for (int ww = 0; ww < 8; ww++) sum += part[(ww * 16 + r) * PSTR + h];
      float a = 1.f / (1.f + __expf(-sum * SCALE));
      ull ad;
      asm("mov.b64 %0, {%1,%1};" : "=l"(ad) : "f"(a));
      attn_d[r * H + h] = ad;
    }
    __syncthreads();

    // ---- Phase 2: out = fea(smem) + bp + attn @ M2.  4 cols/thread ----
    float* ob = out + (size_t)tile * 16384 + c0;
#pragma unroll
    for (int r = 0; r < 16; r++) {
      ulonglong2 f = *reinterpret_cast<const ulonglong2*>(fb + r * TSTR + c0);
      ull oa, oc;
      ADD2(oa, f.x, bpv.x);
      ADD2(oc, f.y, bpv.y);
      const ull* ar = attn_d + r * H;
#pragma unroll
      for (int hg = 0; hg < 8; hg++) {
        ulonglong2 a2 = *reinterpret_cast<const ulonglong2*>(ar + hg * 2);
        FMA2(oa, a2.x, M2[hg * 2].x);
        FMA2(oc, a2.x, M2[hg * 2].y);
        FMA2(oa, a2.y, M2[hg * 2 + 1].x);
        FMA2(oc, a2.y, M2[hg * 2 + 1].y);
      }
      ulonglong2 o;
      o.x = oa;
      o.y = oc;
      *reinterpret_cast<ulonglong2*>(ob + r * 1024) = o;
    }
    __syncthreads();  // all reads of buf(tile&1) done before refill below

    if (tile + 2 < te) { ISSUE_T(tile + 2); }
    COMMIT();  // exactly one commit per iteration (possibly empty)
  }
}

// ---------------------------------------------------------------------------
extern "C" void kernel_launch(void* const* d_in, const int* in_sizes, int n_in,
                              void* d_out, int out_size) {
  const float* fea = (const float*)d_in[0];
  const float* emb = (const float*)d_in[1];
  const float* Wq  = (const float*)d_in[2];
  const float* Wk  = (const float*)d_in[3];
  const float* Wv  = (const float*)d_in[4];
  const float* Wp  = (const float*)d_in[5];
  const float* bp  = (const float*)d_in[6];
  float* out = (float*)d_out;

  cudaFuncSetAttribute(gate_fused, cudaFuncAttributeMaxDynamicSharedMemorySize,
                       SMEM_MAIN);

  precompute_kv<<<1024, 128>>>(emb, Wk, Wv);
  precompute_uM<<<dim3(4, H, 2), 256>>>(Wq, Wp);
  gate_fused<<<NBLK, 256, SMEM_MAIN>>>(fea, bp, out);
}